// round 7
// baseline (speedup 1.0000x reference)
#include <cuda_runtime.h>

// ---------------- problem constants ----------------
#define BB   4
#define NPG  2048        // coarse nodes per graph
#define NNODE 8192
#define MM   65536       // skip nodes
#define MPG  16384
#define EE   131072      // edges
#define EPG  32768
#define TT   16          // tokens per graph
#define FIN  16
#define GDIM 1024
#define EMB  64
#define NH   4
#define HD   16
#define CI   32
#define PDIM 67          // 3 + 64

// ---------------- device scratch (no cudaMalloc allowed) ----------------
__device__ float d_pseudo[EE * PDIM];     // 35 MB
__device__ float d_h0[MM * CI];
__device__ float d_h1[MM * CI];
__device__ float d_aggr[MM * CI];
__device__ int   d_cnt[MM];
__device__ float d_Wt0[PDIM * 1024];
__device__ float d_Wt1[PDIM * 1024];
__device__ float d_Wt2[PDIM * 512];
__device__ float d_pe[TT * EMB];
__device__ float d_A[EMB * 3];
__device__ float d_cc[EMB];
__device__ float d_K2[BB * TT * EMB];
__device__ float d_V2[BB * TT * EMB];
__device__ float d_U[BB * NH * TT * 3];
__device__ float d_s0[BB * NH * TT];
__device__ float d_OV[BB * NH * TT * EMB];

// ---------------- setup kernels ----------------

// pe buffer, A = wq @ Wq_w  [64,3], c = bq + wq @ Wq_b  [64]
__global__ void s1_kernel(const float* __restrict__ ipw, const float* __restrict__ ipb,
                          const float* __restrict__ Wq_w, const float* __restrict__ Wq_b) {
    int t = threadIdx.x;
    for (int idx = t; idx < TT * EMB; idx += blockDim.x) {
        int tt = idx / EMB, j = idx % EMB;
        int i2 = j & ~1;
        float div = expf(-(float)i2 * (9.210340371976184f / (float)EMB)); // ln(10000)
        float ang = (float)tt * div;
        d_pe[idx] = (j & 1) ? cosf(ang) : sinf(ang);
    }
    for (int idx = t; idx < EMB * 3; idx += blockDim.x) {
        int j = idx / 3, p = idx % 3;
        float s = 0.f;
        for (int i = 0; i < EMB; i++) s += ipw[j * EMB + i] * Wq_w[i * 3 + p];
        d_A[idx] = s;
    }
    for (int j = t; j < EMB; j += blockDim.x) {
        float s = ipb[j];
        for (int i = 0; i < EMB; i++) s += ipw[j * EMB + i] * Wq_b[i];
        d_cc[j] = s;
    }
}

// Per (b,t): Kt/Vt (token proj + pe), then K2 = Kt@wk.T+bk, V2 = Vt@wv.T+bv
__global__ void s2_kernel(const float* __restrict__ gt,
                          const float* __restrict__ Wk_w, const float* __restrict__ Wk_b,
                          const float* __restrict__ Wv_w, const float* __restrict__ Wv_b,
                          const float* __restrict__ ipw, const float* __restrict__ ipb) {
    __shared__ float Kt[EMB], Vt[EMB];
    int bt = blockIdx.x;            // b*TT + t
    int tloc = bt % TT;
    int j = threadIdx.x;            // 0..63
    const float* g  = gt + (size_t)bt * GDIM;
    const float* wk = Wk_w + (size_t)j * GDIM;
    const float* wv = Wv_w + (size_t)j * GDIM;
    float sk = 0.f, sv = 0.f;
    for (int i = 0; i < GDIM; i += 4) {
        float4 gv = *(const float4*)(g + i);
        float4 k4 = *(const float4*)(wk + i);
        float4 v4 = *(const float4*)(wv + i);
        sk += gv.x * k4.x + gv.y * k4.y + gv.z * k4.z + gv.w * k4.w;
        sv += gv.x * v4.x + gv.y * v4.y + gv.z * v4.z + gv.w * v4.w;
    }
    Kt[j] = sk + Wk_b[j] + d_pe[tloc * EMB + j];
    Vt[j] = sv + Wv_b[j] + d_pe[tloc * EMB + j];
    __syncthreads();
    const float* wkr = ipw + (size_t)(EMB + j) * EMB;
    const float* wvr = ipw + (size_t)(2 * EMB + j) * EMB;
    float s2k = ipb[EMB + j], s2v = ipb[2 * EMB + j];
    for (int i = 0; i < EMB; i++) { s2k += Kt[i] * wkr[i]; s2v += Vt[i] * wvr[i]; }
    d_K2[bt * EMB + j] = s2k;
    d_V2[bt * EMB + j] = s2v;
}

// Per graph: U[h,t,3] (score-vs-midpoint linear map), s0[h,t], OV[(h,t), j] = out_w-folded V
__global__ void s3_kernel(const float* __restrict__ out_w) {
    int b = blockIdx.x;
    int t = threadIdx.x;
    for (int idx = t; idx < NH * TT * 3; idx += blockDim.x) {
        int p = idx % 3; int ht = idx / 3; int h = ht / TT, tt = ht % TT;
        float s = 0.f;
        for (int d = 0; d < HD; d++)
            s += d_A[(h * HD + d) * 3 + p] * d_K2[(b * TT + tt) * EMB + h * HD + d];
        d_U[b * NH * TT * 3 + idx] = 0.25f * s;
    }
    for (int idx = t; idx < NH * TT; idx += blockDim.x) {
        int h = idx / TT, tt = idx % TT;
        float s = 0.f;
        for (int d = 0; d < HD; d++)
            s += d_cc[h * HD + d] * d_K2[(b * TT + tt) * EMB + h * HD + d];
        d_s0[b * NH * TT + idx] = 0.25f * s;
    }
    for (int idx = t; idx < NH * TT * EMB; idx += blockDim.x) {
        int j = idx % EMB; int ht = idx / EMB; int h = ht / TT, tt = ht % TT;
        float s = 0.f;
        for (int d = 0; d < HD; d++)
            s += out_w[j * EMB + h * HD + d] * d_V2[(b * TT + tt) * EMB + h * HD + d];
        d_OV[b * NH * TT * EMB + idx] = s;
    }
}

// Transpose nn_w [J,67] -> Wt [67,J] so per-edge weight loads are coalesced
__global__ void trans_kernel(const float* __restrict__ nw, int layer) {
    int J = (layer == 2) ? 512 : 1024;
    float* wt = (layer == 0) ? d_Wt0 : (layer == 1) ? d_Wt1 : d_Wt2;
    int idx = blockIdx.x * blockDim.x + threadIdx.x;
    if (idx >= J * PDIM) return;
    int j = idx / PDIM, p = idx - j * PDIM;
    wt[p * J + j] = nw[j * PDIM + p];
}

// ---------------- stage A: knn interpolate + concat ----------------
__global__ void knn_kernel(const float* __restrict__ x, const float* __restrict__ pos,
                           const float* __restrict__ x_skip, const float* __restrict__ pos_skip) {
    __shared__ float cx[NPG], cy[NPG], cz[NPG], cn2[NPG];
    int m = blockIdx.x * blockDim.x + threadIdx.x;
    int b = m / MPG;
    const float* cp = pos + (size_t)b * NPG * 3;
    for (int j = threadIdx.x; j < NPG; j += blockDim.x) {
        float X = cp[j * 3], Y = cp[j * 3 + 1], Z = cp[j * 3 + 2];
        cx[j] = X; cy[j] = Y; cz[j] = Z; cn2[j] = X * X + Y * Y + Z * Z;
    }
    __syncthreads();
    float px = pos_skip[m * 3], py = pos_skip[m * 3 + 1], pz = pos_skip[m * 3 + 2];
    float ps2 = px * px + py * py + pz * pz;
    float b0 = 1e30f, b1 = 1e30f, b2 = 1e30f;
    int i0 = 0, i1 = 0, i2 = 0;
    for (int j = 0; j < NPG; j++) {
        float d = ps2 + cn2[j] - 2.f * (px * cx[j] + py * cy[j] + pz * cz[j]);
        if (d < b2) {
            if (d < b1) {
                b2 = b1; i2 = i1;
                if (d < b0) { b1 = b0; i1 = i0; b0 = d; i0 = j; }
                else        { b1 = d;  i1 = j; }
            } else { b2 = d; i2 = j; }
        }
    }
    float w0 = 1.f / fmaxf(b0, 1e-16f);
    float w1 = 1.f / fmaxf(b1, 1e-16f);
    float w2 = 1.f / fmaxf(b2, 1e-16f);
    float inv = 1.f / (w0 + w1 + w2);
    const float* x0 = x + (size_t)(b * NPG + i0) * FIN;
    const float* x1 = x + (size_t)(b * NPG + i1) * FIN;
    const float* x2 = x + (size_t)(b * NPG + i2) * FIN;
    const float* xs = x_skip + (size_t)m * FIN;
    float* h = d_h0 + (size_t)m * CI;
    #pragma unroll
    for (int f = 0; f < FIN; f++) {
        h[f]       = (w0 * x0[f] + w1 * x1[f] + w2 * x2[f]) * inv;
        h[FIN + f] = xs[f];
    }
}

// ---------------- degree ----------------
__global__ void zero_cnt_kernel() { d_cnt[blockIdx.x * blockDim.x + threadIdx.x] = 0; }
__global__ void deg_kernel(const int* __restrict__ ei) {
    int e = blockIdx.x * blockDim.x + threadIdx.x;
    if (e < EE) atomicAdd(&d_cnt[ei[EE + e]], 1);
}

// ---------------- stage B: per-edge attention -> pseudo [E,67] ----------------
__global__ void attn_kernel(const int* __restrict__ ei, const float* __restrict__ pos_skip,
                            const float* __restrict__ out_b) {
    __shared__ float4 sOV4[NH * TT * EMB / 4];
    __shared__ float sU[NH * TT * 3], sS0[NH * TT], sOB[EMB];
    int e = blockIdx.x * blockDim.x + threadIdx.x;
    int b = blockIdx.x / (EPG / 256);
    float* sOV = (float*)sOV4;
    for (int i = threadIdx.x; i < NH * TT * EMB; i += 256) sOV[i] = d_OV[b * NH * TT * EMB + i];
    for (int i = threadIdx.x; i < NH * TT * 3;  i += 256) sU[i]  = d_U[b * NH * TT * 3 + i];
    for (int i = threadIdx.x; i < NH * TT;      i += 256) sS0[i] = d_s0[b * NH * TT + i];
    for (int i = threadIdx.x; i < EMB;          i += 256) sOB[i] = out_b[i];
    __syncthreads();
    int s = ei[e], d = ei[EE + e];
    float sx = pos_skip[s * 3], sy = pos_skip[s * 3 + 1], sz = pos_skip[s * 3 + 2];
    float dx = pos_skip[d * 3], dy = pos_skip[d * 3 + 1], dz = pos_skip[d * 3 + 2];
    float epx = 0.5f * (dx + sx), epy = 0.5f * (dy + sy), epz = 0.5f * (dz + sz);
    float4 o4[EMB / 4];
    #pragma unroll
    for (int q = 0; q < EMB / 4; q++) {
        o4[q].x = sOB[4 * q]; o4[q].y = sOB[4 * q + 1];
        o4[q].z = sOB[4 * q + 2]; o4[q].w = sOB[4 * q + 3];
    }
    #pragma unroll
    for (int h = 0; h < NH; h++) {
        float sc[TT];
        float mx = -1e30f;
        #pragma unroll
        for (int t = 0; t < TT; t++) {
            int ht = h * TT + t;
            sc[t] = sS0[ht] + epx * sU[ht * 3] + epy * sU[ht * 3 + 1] + epz * sU[ht * 3 + 2];
            mx = fmaxf(mx, sc[t]);
        }
        float se = 0.f;
        #pragma unroll
        for (int t = 0; t < TT; t++) { sc[t] = __expf(sc[t] - mx); se += sc[t]; }
        float inv = 1.f / se;
        #pragma unroll
        for (int t = 0; t < TT; t++) {
            float a = sc[t] * inv;
            const float4* row = sOV4 + (h * TT + t) * (EMB / 4);
            #pragma unroll
            for (int q = 0; q < EMB / 4; q++) {
                float4 v = row[q];
                o4[q].x += a * v.x; o4[q].y += a * v.y;
                o4[q].z += a * v.z; o4[q].w += a * v.w;
            }
        }
    }
    float* pd = d_pseudo + (size_t)e * PDIM;
    pd[0] = dx - sx; pd[1] = dy - sy; pd[2] = dz - sz;
    #pragma unroll
    for (int q = 0; q < EMB / 4; q++) {
        pd[3 + 4 * q] = o4[q].x; pd[4 + 4 * q] = o4[q].y;
        pd[5 + 4 * q] = o4[q].z; pd[6 + 4 * q] = o4[q].w;
    }
}

// ---------------- stage C: fused edge MLP + message + scatter ----------------
__global__ void zero_aggr_kernel() { d_aggr[blockIdx.x * blockDim.x + threadIdx.x] = 0.f; }

template <int CO>
__global__ void __launch_bounds__(CO * 8)
edge_kernel(int layer, const int* __restrict__ ei, const float* __restrict__ nb) {
    constexpr int NT = CO * 8;
    constexpr int BE = 64;    // edges per block
    constexpr int GE = 8;     // edges per thread
    constexpr int J  = CI * CO;
    __shared__ float ps_s[BE * 69];
    __shared__ float hs_s[BE * 33];
    __shared__ float nb_s[J];
    __shared__ int   dst_s[BE];

    const float* Wt  = (layer == 0) ? d_Wt0 : (layer == 1) ? d_Wt1 : d_Wt2;
    const float* hin = (layer == 1) ? d_h1 : d_h0;

    int e0 = blockIdx.x * BE;
    for (int idx = threadIdx.x; idx < BE * PDIM; idx += NT) {
        int el = idx / PDIM, p = idx - el * PDIM;
        ps_s[el * 69 + p] = d_pseudo[(size_t)(e0 + el) * PDIM + p];
    }
    for (int idx = threadIdx.x; idx < BE * CI; idx += NT) {
        int el = idx >> 5, i = idx & 31;
        hs_s[el * 33 + i] = hin[(size_t)ei[e0 + el] * CI + i];
    }
    for (int idx = threadIdx.x; idx < BE; idx += NT) dst_s[idx] = ei[EE + e0 + idx];
    for (int idx = threadIdx.x; idx < J; idx += NT) nb_s[idx] = nb[idx];
    __syncthreads();

    int o = threadIdx.x % CO;
    int g = threadIdx.x / CO;
    const float* psg = ps_s + g * GE * 69;
    const float* hsg = hs_s + g * GE * 33;
    float msg[GE];
    #pragma unroll
    for (int k = 0; k < GE; k++) msg[k] = 0.f;

    #pragma unroll 1
    for (int ic = 0; ic < CI; ic += 8) {
        float z[8][GE];
        #pragma unroll
        for (int i = 0; i < 8; i++) {
            float nbv = nb_s[(ic + i) * CO + o];
            #pragma unroll
            for (int k = 0; k < GE; k++) z[i][k] = nbv;
        }
        const float* wp = Wt + ic * CO + o;
        #pragma unroll 2
        for (int p = 0; p < PDIM; p++) {
            float w[8];
            #pragma unroll
            for (int i = 0; i < 8; i++) w[i] = wp[i * CO];
            float a[GE];
            #pragma unroll
            for (int k = 0; k < GE; k++) a[k] = psg[k * 69 + p];
            #pragma unroll
            for (int i = 0; i < 8; i++)
                #pragma unroll
                for (int k = 0; k < GE; k++) z[i][k] = fmaf(a[k], w[i], z[i][k]);
            wp += J;
        }
        #pragma unroll
        for (int i = 0; i < 8; i++)
            #pragma unroll
            for (int k = 0; k < GE; k++)
                msg[k] += hsg[k * 33 + ic + i] * fmaxf(z[i][k], 0.f);
    }
    #pragma unroll
    for (int k = 0; k < GE; k++)
        atomicAdd(&d_aggr[(size_t)dst_s[g * GE + k] * CO + o], msg[k]);
}

// node update: h_out = relu(aggr/cnt + h_in @ root + bias)
template <int CO>
__global__ void node_kernel(int layer, const float* __restrict__ root,
                            const float* __restrict__ bias, float* __restrict__ finalout,
                            int out_size) {
    __shared__ float4 root4[CI * CO / 4];
    __shared__ float  bias_s[CO];
    for (int i = threadIdx.x; i < CI * CO / 4; i += blockDim.x) root4[i] = ((const float4*)root)[i];
    for (int i = threadIdx.x; i < CO; i += blockDim.x) bias_s[i] = bias[i];
    __syncthreads();

    const float* hin = (layer == 1) ? d_h1 : d_h0;
    int v = blockIdx.x * blockDim.x + threadIdx.x;
    float inv = 1.f / (float)max(d_cnt[v], 1);

    float4 acc[CO / 4];
    #pragma unroll
    for (int q = 0; q < CO / 4; q++) {
        float4 ag = ((const float4*)(d_aggr + (size_t)v * CO))[q];
        acc[q].x = bias_s[4 * q]     + ag.x * inv;
        acc[q].y = bias_s[4 * q + 1] + ag.y * inv;
        acc[q].z = bias_s[4 * q + 2] + ag.z * inv;
        acc[q].w = bias_s[4 * q + 3] + ag.w * inv;
    }
    float hv[CI];
    #pragma unroll
    for (int q = 0; q < CI / 4; q++) {
        float4 t = ((const float4*)(hin + (size_t)v * CI))[q];
        hv[4 * q] = t.x; hv[4 * q + 1] = t.y; hv[4 * q + 2] = t.z; hv[4 * q + 3] = t.w;
    }
    #pragma unroll
    for (int i = 0; i < CI; i++) {
        #pragma unroll
        for (int q = 0; q < CO / 4; q++) {
            float4 r = root4[i * (CO / 4) + q];
            acc[q].x = fmaf(hv[i], r.x, acc[q].x);
            acc[q].y = fmaf(hv[i], r.y, acc[q].y);
            acc[q].z = fmaf(hv[i], r.z, acc[q].z);
            acc[q].w = fmaf(hv[i], r.w, acc[q].w);
        }
    }
    float* hout = (layer == 0) ? d_h1 : (layer == 1) ? d_h0 : finalout;
    #pragma unroll
    for (int q = 0; q < CO / 4; q++) {
        float4 r;
        r.x = fmaxf(acc[q].x, 0.f); r.y = fmaxf(acc[q].y, 0.f);
        r.z = fmaxf(acc[q].z, 0.f); r.w = fmaxf(acc[q].w, 0.f);
        if (layer == 2) {
            int ofs = v * CO + 4 * q;
            if (ofs + 4 <= out_size) ((float4*)(hout + ofs))[0] = r;
        } else {
            ((float4*)(hout + (size_t)v * CO))[q] = r;
        }
    }
}

// remaining reference outputs (pos_skip, batch_skip) if the harness expects them
__global__ void tail_kernel(const float* __restrict__ pos_skip, const int* __restrict__ batch_skip,
                            float* __restrict__ out, int out_size) {
    int i = blockIdx.x * blockDim.x + threadIdx.x;
    int base = MM * 16;
    if (i < MM * 3 && base + i < out_size) out[base + i] = pos_skip[i];
    int base2 = base + MM * 3;
    if (i < MM && base2 + i < out_size) out[base2 + i] = (float)batch_skip[i];
}

// ---------------- launch ----------------
extern "C" void kernel_launch(void* const* d_in, const int* in_sizes, int n_in,
                              void* d_out, int out_size) {
    const float* x        = (const float*)d_in[0];
    const float* pos      = (const float*)d_in[1];
    const float* x_skip   = (const float*)d_in[3];
    const float* pos_skip = (const float*)d_in[4];
    const int*   batch_sk = (const int*)  d_in[5];
    const int*   ei       = (const int*)  d_in[6];
    const float* gt       = (const float*)d_in[7];
    const float* Wq_w = (const float*)d_in[8];   const float* Wq_b = (const float*)d_in[9];
    const float* Wk_w = (const float*)d_in[10];  const float* Wk_b = (const float*)d_in[11];
    const float* Wv_w = (const float*)d_in[12];  const float* Wv_b = (const float*)d_in[13];
    const float* ipw  = (const float*)d_in[14];  const float* ipb  = (const float*)d_in[15];
    const float* ow   = (const float*)d_in[16];  const float* ob   = (const float*)d_in[17];
    const float* nw0 = (const float*)d_in[18]; const float* nb0 = (const float*)d_in[19];
    const float* rt0 = (const float*)d_in[20]; const float* bs0 = (const float*)d_in[21];
    const float* nw1 = (const float*)d_in[22]; const float* nb1 = (const float*)d_in[23];
    const float* rt1 = (const float*)d_in[24]; const float* bs1 = (const float*)d_in[25];
    const float* nw2 = (const float*)d_in[26]; const float* nb2 = (const float*)d_in[27];
    const float* rt2 = (const float*)d_in[28]; const float* bs2 = (const float*)d_in[29];
    float* out = (float*)d_out;

    // setup (tiny)
    s1_kernel<<<1, 256>>>(ipw, ipb, Wq_w, Wq_b);
    s2_kernel<<<BB * TT, EMB>>>(gt, Wk_w, Wk_b, Wv_w, Wv_b, ipw, ipb);
    s3_kernel<<<BB, 256>>>(ow);
    trans_kernel<<<(1024 * PDIM + 255) / 256, 256>>>(nw0, 0);
    trans_kernel<<<(1024 * PDIM + 255) / 256, 256>>>(nw1, 1);
    trans_kernel<<<(512  * PDIM + 255) / 256, 256>>>(nw2, 2);

    // stage A: knn interpolate + concat -> d_h0
    knn_kernel<<<MM / 256, 256>>>(x, pos, x_skip, pos_skip);

    // degree
    zero_cnt_kernel<<<MM / 256, 256>>>();
    deg_kernel<<<EE / 256, 256>>>(ei);

    // stage B: attention -> d_pseudo
    attn_kernel<<<EE / 256, 256>>>(ei, pos_skip, ob);

    // stage C: 3 NNConv layers
    // layer 0: d_h0 -> d_h1  (CO=32)
    zero_aggr_kernel<<<MM * CI / 256, 256>>>();
    edge_kernel<32><<<EE / 64, 256>>>(0, ei, nb0);
    node_kernel<32><<<MM / 256, 256>>>(0, rt0, bs0, nullptr, 0);
    // layer 1: d_h1 -> d_h0  (CO=32)
    zero_aggr_kernel<<<MM * CI / 256, 256>>>();
    edge_kernel<32><<<EE / 64, 256>>>(1, ei, nb1);
    node_kernel<32><<<MM / 256, 256>>>(1, rt1, bs1, nullptr, 0);
    // layer 2: d_h0 -> d_out  (CO=16)
    zero_aggr_kernel<<<MM * CI / 256, 256>>>();
    edge_kernel<16><<<EE / 64, 128>>>(2, ei, nb2);
    node_kernel<16><<<MM / 256, 256>>>(2, rt2, bs2, out, out_size);

    // remaining tuple outputs if expected
    tail_kernel<<<(MM * 3 + 255) / 256, 256>>>(pos_skip, batch_sk, out, out_size);
}

// round 8
// speedup vs baseline: 1.1943x; 1.1943x over previous
#include <cuda_runtime.h>

// ---------------- problem constants ----------------
#define BB   4
#define NPG  2048        // coarse nodes per graph
#define MM   65536       // skip nodes
#define MPG  16384
#define EE   131072      // edges
#define EPG  32768
#define TT   16          // tokens per graph
#define FIN  16
#define GDIM 1024
#define EMB  64
#define NH   4
#define HD   16
#define CI   32
#define PDIM 67          // 3 + 64
#define P2N  34          // padded p-pairs (68/2)

typedef unsigned long long ull;

// ---------------- device scratch (no cudaMalloc allowed) ----------------
__device__ float d_pseudo[EE * PDIM];     // 35 MB
__device__ float d_h0[MM * CI];
__device__ float d_h1[MM * CI];
__device__ float d_aggr[MM * CI];
__device__ int   d_cnt[MM];
__device__ __align__(16) float d_Wt0[P2N * 1024 * 2];   // p-paired layout [p2][j][2]
__device__ __align__(16) float d_Wt1[P2N * 1024 * 2];
__device__ __align__(16) float d_Wt2[P2N * 512 * 2];
__device__ float d_pe[TT * EMB];
__device__ float d_A[EMB * 3];
__device__ float d_cc[EMB];
__device__ float d_K2[BB * TT * EMB];
__device__ float d_V2[BB * TT * EMB];
__device__ float d_U[BB * NH * TT * 3];
__device__ float d_s0[BB * NH * TT];
__device__ float d_OV[BB * NH * TT * EMB];

// ---------------- packed f32x2 helpers ----------------
__device__ __forceinline__ void fma2(ull& d, ull a, ull b) {
    asm("fma.rn.f32x2 %0, %1, %2, %0;" : "+l"(d) : "l"(a), "l"(b));
}
__device__ __forceinline__ float red2(ull v) {
    float lo, hi;
    asm("mov.b64 {%0, %1}, %2;" : "=f"(lo), "=f"(hi) : "l"(v));
    return lo + hi;
}

// ---------------- setup kernels ----------------

// pe buffer, A = wq @ Wq_w  [64,3], c = bq + wq @ Wq_b  [64]
__global__ void s1_kernel(const float* __restrict__ ipw, const float* __restrict__ ipb,
                          const float* __restrict__ Wq_w, const float* __restrict__ Wq_b) {
    int t = threadIdx.x;
    for (int idx = t; idx < TT * EMB; idx += blockDim.x) {
        int tt = idx / EMB, j = idx % EMB;
        int i2 = j & ~1;
        float div = expf(-(float)i2 * (9.210340371976184f / (float)EMB)); // ln(10000)
        float ang = (float)tt * div;
        d_pe[idx] = (j & 1) ? cosf(ang) : sinf(ang);
    }
    for (int idx = t; idx < EMB * 3; idx += blockDim.x) {
        int j = idx / 3, p = idx % 3;
        float s = 0.f;
        for (int i = 0; i < EMB; i++) s += ipw[j * EMB + i] * Wq_w[i * 3 + p];
        d_A[idx] = s;
    }
    for (int j = t; j < EMB; j += blockDim.x) {
        float s = ipb[j];
        for (int i = 0; i < EMB; i++) s += ipw[j * EMB + i] * Wq_b[i];
        d_cc[j] = s;
    }
}

// Per (b,t): Kt/Vt (token proj + pe), then K2 = Kt@wk.T+bk, V2 = Vt@wv.T+bv
__global__ void s2_kernel(const float* __restrict__ gt,
                          const float* __restrict__ Wk_w, const float* __restrict__ Wk_b,
                          const float* __restrict__ Wv_w, const float* __restrict__ Wv_b,
                          const float* __restrict__ ipw, const float* __restrict__ ipb) {
    __shared__ float Kt[EMB], Vt[EMB];
    int bt = blockIdx.x;            // b*TT + t
    int tloc = bt % TT;
    int j = threadIdx.x;            // 0..63
    const float* g  = gt + (size_t)bt * GDIM;
    const float* wk = Wk_w + (size_t)j * GDIM;
    const float* wv = Wv_w + (size_t)j * GDIM;
    float sk = 0.f, sv = 0.f;
    for (int i = 0; i < GDIM; i += 4) {
        float4 gv = *(const float4*)(g + i);
        float4 k4 = *(const float4*)(wk + i);
        float4 v4 = *(const float4*)(wv + i);
        sk += gv.x * k4.x + gv.y * k4.y + gv.z * k4.z + gv.w * k4.w;
        sv += gv.x * v4.x + gv.y * v4.y + gv.z * v4.z + gv.w * v4.w;
    }
    Kt[j] = sk + Wk_b[j] + d_pe[tloc * EMB + j];
    Vt[j] = sv + Wv_b[j] + d_pe[tloc * EMB + j];
    __syncthreads();
    const float* wkr = ipw + (size_t)(EMB + j) * EMB;
    const float* wvr = ipw + (size_t)(2 * EMB + j) * EMB;
    float s2k = ipb[EMB + j], s2v = ipb[2 * EMB + j];
    for (int i = 0; i < EMB; i++) { s2k += Kt[i] * wkr[i]; s2v += Vt[i] * wvr[i]; }
    d_K2[bt * EMB + j] = s2k;
    d_V2[bt * EMB + j] = s2v;
}

// Per graph: U[h,t,3], s0[h,t], OV[(h,t), j] = out_w-folded V
__global__ void s3_kernel(const float* __restrict__ out_w) {
    int b = blockIdx.x;
    int t = threadIdx.x;
    for (int idx = t; idx < NH * TT * 3; idx += blockDim.x) {
        int p = idx % 3; int ht = idx / 3; int h = ht / TT, tt = ht % TT;
        float s = 0.f;
        for (int d = 0; d < HD; d++)
            s += d_A[(h * HD + d) * 3 + p] * d_K2[(b * TT + tt) * EMB + h * HD + d];
        d_U[b * NH * TT * 3 + idx] = 0.25f * s;
    }
    for (int idx = t; idx < NH * TT; idx += blockDim.x) {
        int h = idx / TT, tt = idx % TT;
        float s = 0.f;
        for (int d = 0; d < HD; d++)
            s += d_cc[h * HD + d] * d_K2[(b * TT + tt) * EMB + h * HD + d];
        d_s0[b * NH * TT + idx] = 0.25f * s;
    }
    for (int idx = t; idx < NH * TT * EMB; idx += blockDim.x) {
        int j = idx % EMB; int ht = idx / EMB; int h = ht / TT, tt = ht % TT;
        float s = 0.f;
        for (int d = 0; d < HD; d++)
            s += out_w[j * EMB + h * HD + d] * d_V2[(b * TT + tt) * EMB + h * HD + d];
        d_OV[b * NH * TT * EMB + idx] = s;
    }
}

// Build p-paired, transposed weights: Wt[p2][j][2] = { nw[j][2p2], nw[j][2p2+1] or 0 }
__global__ void trans_kernel(const float* __restrict__ nw, int layer) {
    int J = (layer == 2) ? 512 : 1024;
    float* wt = (layer == 0) ? d_Wt0 : (layer == 1) ? d_Wt1 : d_Wt2;
    int idx = blockIdx.x * blockDim.x + threadIdx.x;
    if (idx >= P2N * J) return;
    int p2 = idx / J, j = idx - p2 * J;
    float lo = nw[j * PDIM + 2 * p2];
    float hi = (2 * p2 + 1 < PDIM) ? nw[j * PDIM + 2 * p2 + 1] : 0.f;
    wt[idx * 2] = lo;
    wt[idx * 2 + 1] = hi;
}

// ---------------- stage A: knn interpolate + concat ----------------
__global__ void knn_kernel(const float* __restrict__ x, const float* __restrict__ pos,
                           const float* __restrict__ x_skip, const float* __restrict__ pos_skip) {
    __shared__ float cx[NPG], cy[NPG], cz[NPG], cn2[NPG];
    int m = blockIdx.x * blockDim.x + threadIdx.x;
    int b = m / MPG;
    const float* cp = pos + (size_t)b * NPG * 3;
    for (int j = threadIdx.x; j < NPG; j += blockDim.x) {
        float X = cp[j * 3], Y = cp[j * 3 + 1], Z = cp[j * 3 + 2];
        cx[j] = X; cy[j] = Y; cz[j] = Z; cn2[j] = X * X + Y * Y + Z * Z;
    }
    __syncthreads();
    float px = pos_skip[m * 3], py = pos_skip[m * 3 + 1], pz = pos_skip[m * 3 + 2];
    float ps2 = px * px + py * py + pz * pz;
    float b0 = 1e30f, b1 = 1e30f, b2 = 1e30f;
    int i0 = 0, i1 = 0, i2 = 0;
    for (int j = 0; j < NPG; j++) {
        float d = ps2 + cn2[j] - 2.f * (px * cx[j] + py * cy[j] + pz * cz[j]);
        if (d < b2) {
            if (d < b1) {
                b2 = b1; i2 = i1;
                if (d < b0) { b1 = b0; i1 = i0; b0 = d; i0 = j; }
                else        { b1 = d;  i1 = j; }
            } else { b2 = d; i2 = j; }
        }
    }
    float w0 = 1.f / fmaxf(b0, 1e-16f);
    float w1 = 1.f / fmaxf(b1, 1e-16f);
    float w2 = 1.f / fmaxf(b2, 1e-16f);
    float inv = 1.f / (w0 + w1 + w2);
    const float* x0 = x + (size_t)(b * NPG + i0) * FIN;
    const float* x1 = x + (size_t)(b * NPG + i1) * FIN;
    const float* x2 = x + (size_t)(b * NPG + i2) * FIN;
    const float* xs = x_skip + (size_t)m * FIN;
    float* h = d_h0 + (size_t)m * CI;
    #pragma unroll
    for (int f = 0; f < FIN; f++) {
        h[f]       = (w0 * x0[f] + w1 * x1[f] + w2 * x2[f]) * inv;
        h[FIN + f] = xs[f];
    }
}

// ---------------- degree ----------------
__global__ void zero_cnt_kernel() { d_cnt[blockIdx.x * blockDim.x + threadIdx.x] = 0; }
__global__ void deg_kernel(const int* __restrict__ ei) {
    int e = blockIdx.x * blockDim.x + threadIdx.x;
    if (e < EE) atomicAdd(&d_cnt[ei[EE + e]], 1);
}

// ---------------- stage B: per-edge attention -> pseudo [E,67] ----------------
__global__ void attn_kernel(const int* __restrict__ ei, const float* __restrict__ pos_skip,
                            const float* __restrict__ out_b) {
    __shared__ float4 sOV4[NH * TT * EMB / 4];
    __shared__ float sU[NH * TT * 3], sS0[NH * TT], sOB[EMB];
    int e = blockIdx.x * blockDim.x + threadIdx.x;
    int b = blockIdx.x / (EPG / 256);
    float* sOV = (float*)sOV4;
    for (int i = threadIdx.x; i < NH * TT * EMB; i += 256) sOV[i] = d_OV[b * NH * TT * EMB + i];
    for (int i = threadIdx.x; i < NH * TT * 3;  i += 256) sU[i]  = d_U[b * NH * TT * 3 + i];
    for (int i = threadIdx.x; i < NH * TT;      i += 256) sS0[i] = d_s0[b * NH * TT + i];
    for (int i = threadIdx.x; i < EMB;          i += 256) sOB[i] = out_b[i];
    __syncthreads();
    int s = ei[e], d = ei[EE + e];
    float sx = pos_skip[s * 3], sy = pos_skip[s * 3 + 1], sz = pos_skip[s * 3 + 2];
    float dx = pos_skip[d * 3], dy = pos_skip[d * 3 + 1], dz = pos_skip[d * 3 + 2];
    float epx = 0.5f * (dx + sx), epy = 0.5f * (dy + sy), epz = 0.5f * (dz + sz);
    float4 o4[EMB / 4];
    #pragma unroll
    for (int q = 0; q < EMB / 4; q++) {
        o4[q].x = sOB[4 * q]; o4[q].y = sOB[4 * q + 1];
        o4[q].z = sOB[4 * q + 2]; o4[q].w = sOB[4 * q + 3];
    }
    #pragma unroll
    for (int h = 0; h < NH; h++) {
        float sc[TT];
        float mx = -1e30f;
        #pragma unroll
        for (int t = 0; t < TT; t++) {
            int ht = h * TT + t;
            sc[t] = sS0[ht] + epx * sU[ht * 3] + epy * sU[ht * 3 + 1] + epz * sU[ht * 3 + 2];
            mx = fmaxf(mx, sc[t]);
        }
        float se = 0.f;
        #pragma unroll
        for (int t = 0; t < TT; t++) { sc[t] = __expf(sc[t] - mx); se += sc[t]; }
        float inv = 1.f / se;
        #pragma unroll
        for (int t = 0; t < TT; t++) {
            float a = sc[t] * inv;
            const float4* row = sOV4 + (h * TT + t) * (EMB / 4);
            #pragma unroll
            for (int q = 0; q < EMB / 4; q++) {
                float4 v = row[q];
                o4[q].x += a * v.x; o4[q].y += a * v.y;
                o4[q].z += a * v.z; o4[q].w += a * v.w;
            }
        }
    }
    float* pd = d_pseudo + (size_t)e * PDIM;
    pd[0] = dx - sx; pd[1] = dy - sy; pd[2] = dz - sz;
    #pragma unroll
    for (int q = 0; q < EMB / 4; q++) {
        pd[3 + 4 * q] = o4[q].x; pd[4 + 4 * q] = o4[q].y;
        pd[5 + 4 * q] = o4[q].z; pd[6 + 4 * q] = o4[q].w;
    }
}

// ---------------- stage C: fused edge MLP (packed f32x2) + message + scatter ----------------
__global__ void zero_aggr_kernel() { d_aggr[blockIdx.x * blockDim.x + threadIdx.x] = 0.f; }

template <int CO>
__global__ void __launch_bounds__(CO * 8)
edge_kernel(int layer, const int* __restrict__ ei, const float* __restrict__ nb) {
    constexpr int NT = CO * 8;
    constexpr int BE = 64;    // edges per block
    constexpr int GE = 8;     // edges per thread
    constexpr int J  = CI * CO;
    __shared__ __align__(16) float ps_s[BE * 70];   // p-padded rows (67..69 zero)
    __shared__ float hs_s[BE * 33];
    __shared__ float nb_s[J];
    __shared__ int   dst_s[BE];

    const float* Wt  = (layer == 0) ? d_Wt0 : (layer == 1) ? d_Wt1 : d_Wt2;
    const float* hin = (layer == 1) ? d_h1 : d_h0;

    int e0 = blockIdx.x * BE;
    for (int idx = threadIdx.x; idx < BE * 70; idx += NT) {
        int el = idx / 70, p = idx - el * 70;
        ps_s[idx] = (p < PDIM) ? d_pseudo[(size_t)(e0 + el) * PDIM + p] : 0.f;
    }
    for (int idx = threadIdx.x; idx < BE * CI; idx += NT) {
        int el = idx >> 5, i = idx & 31;
        hs_s[el * 33 + i] = hin[(size_t)ei[e0 + el] * CI + i];
    }
    for (int idx = threadIdx.x; idx < BE; idx += NT) dst_s[idx] = ei[EE + e0 + idx];
    for (int idx = threadIdx.x; idx < J; idx += NT) nb_s[idx] = nb[idx];
    __syncthreads();

    int o = threadIdx.x % CO;
    int g = threadIdx.x / CO;
    const ull* psg2 = (const ull*)(ps_s + g * GE * 70);   // row stride 35 ulls
    const float* hsg = hs_s + g * GE * 33;
    float msg[GE];
    #pragma unroll
    for (int k = 0; k < GE; k++) msg[k] = 0.f;

    #pragma unroll 1
    for (int ic = 0; ic < CI; ic += 4) {
        ull z2[4][GE];
        #pragma unroll
        for (int i = 0; i < 4; i++)
            #pragma unroll
            for (int k = 0; k < GE; k++) z2[i][k] = 0ull;

        const ull* wp = (const ull*)Wt + ic * CO + o;   // stride J ulls per p2
        #pragma unroll 2
        for (int p2 = 0; p2 < P2N; p2++) {
            ull w2[4];
            #pragma unroll
            for (int i = 0; i < 4; i++) w2[i] = wp[i * CO];
            ull a2[GE];
            #pragma unroll
            for (int k = 0; k < GE; k++) a2[k] = psg2[k * 35 + p2];
            #pragma unroll
            for (int i = 0; i < 4; i++)
                #pragma unroll
                for (int k = 0; k < GE; k++) fma2(z2[i][k], a2[k], w2[i]);
            wp += J;
        }
        #pragma unroll
        for (int i = 0; i < 4; i++) {
            float nbv = nb_s[(ic + i) * CO + o];
            #pragma unroll
            for (int k = 0; k < GE; k++) {
                float z = red2(z2[i][k]) + nbv;
                msg[k] = fmaf(hsg[k * 33 + ic + i], fmaxf(z, 0.f), msg[k]);
            }
        }
    }
    #pragma unroll
    for (int k = 0; k < GE; k++)
        atomicAdd(&d_aggr[(size_t)dst_s[g * GE + k] * CO + o], msg[k]);
}

// node update: h_out = relu(aggr/cnt + h_in @ root + bias)
template <int CO>
__global__ void node_kernel(int layer, const float* __restrict__ root,
                            const float* __restrict__ bias, float* __restrict__ finalout,
                            int out_size) {
    __shared__ float4 root4[CI * CO / 4];
    __shared__ float  bias_s[CO];
    for (int i = threadIdx.x; i < CI * CO / 4; i += blockDim.x) root4[i] = ((const float4*)root)[i];
    for (int i = threadIdx.x; i < CO; i += blockDim.x) bias_s[i] = bias[i];
    __syncthreads();

    const float* hin = (layer == 1) ? d_h1 : d_h0;
    int v = blockIdx.x * blockDim.x + threadIdx.x;
    float inv = 1.f / (float)max(d_cnt[v], 1);

    float4 acc[CO / 4];
    #pragma unroll
    for (int q = 0; q < CO / 4; q++) {
        float4 ag = ((const float4*)(d_aggr + (size_t)v * CO))[q];
        acc[q].x = bias_s[4 * q]     + ag.x * inv;
        acc[q].y = bias_s[4 * q + 1] + ag.y * inv;
        acc[q].z = bias_s[4 * q + 2] + ag.z * inv;
        acc[q].w = bias_s[4 * q + 3] + ag.w * inv;
    }
    float hv[CI];
    #pragma unroll
    for (int q = 0; q < CI / 4; q++) {
        float4 t = ((const float4*)(hin + (size_t)v * CI))[q];
        hv[4 * q] = t.x; hv[4 * q + 1] = t.y; hv[4 * q + 2] = t.z; hv[4 * q + 3] = t.w;
    }
    #pragma unroll
    for (int i = 0; i < CI; i++) {
        #pragma unroll
        for (int q = 0; q < CO / 4; q++) {
            float4 r = root4[i * (CO / 4) + q];
            acc[q].x = fmaf(hv[i], r.x, acc[q].x);
            acc[q].y = fmaf(hv[i], r.y, acc[q].y);
            acc[q].z = fmaf(hv[i], r.z, acc[q].z);
            acc[q].w = fmaf(hv[i], r.w, acc[q].w);
        }
    }
    float* hout = (layer == 0) ? d_h1 : (layer == 1) ? d_h0 : finalout;
    #pragma unroll
    for (int q = 0; q < CO / 4; q++) {
        float4 r;
        r.x = fmaxf(acc[q].x, 0.f); r.y = fmaxf(acc[q].y, 0.f);
        r.z = fmaxf(acc[q].z, 0.f); r.w = fmaxf(acc[q].w, 0.f);
        if (layer == 2) {
            int ofs = v * CO + 4 * q;
            if (ofs + 4 <= out_size) ((float4*)(hout + ofs))[0] = r;
        } else {
            ((float4*)(hout + (size_t)v * CO))[q] = r;
        }
    }
}

// remaining reference outputs (pos_skip, batch_skip) if the harness expects them
__global__ void tail_kernel(const float* __restrict__ pos_skip, const int* __restrict__ batch_skip,
                            float* __restrict__ out, int out_size) {
    int i = blockIdx.x * blockDim.x + threadIdx.x;
    int base = MM * 16;
    if (i < MM * 3 && base + i < out_size) out[base + i] = pos_skip[i];
    int base2 = base + MM * 3;
    if (i < MM && base2 + i < out_size) out[base2 + i] = (float)batch_skip[i];
}

// ---------------- launch ----------------
extern "C" void kernel_launch(void* const* d_in, const int* in_sizes, int n_in,
                              void* d_out, int out_size) {
    const float* x        = (const float*)d_in[0];
    const float* pos      = (const float*)d_in[1];
    const float* x_skip   = (const float*)d_in[3];
    const float* pos_skip = (const float*)d_in[4];
    const int*   batch_sk = (const int*)  d_in[5];
    const int*   ei       = (const int*)  d_in[6];
    const float* gt       = (const float*)d_in[7];
    const float* Wq_w = (const float*)d_in[8];   const float* Wq_b = (const float*)d_in[9];
    const float* Wk_w = (const float*)d_in[10];  const float* Wk_b = (const float*)d_in[11];
    const float* Wv_w = (const float*)d_in[12];  const float* Wv_b = (const float*)d_in[13];
    const float* ipw  = (const float*)d_in[14];  const float* ipb  = (const float*)d_in[15];
    const float* ow   = (const float*)d_in[16];  const float* ob   = (const float*)d_in[17];
    const float* nw0 = (const float*)d_in[18]; const float* nb0 = (const float*)d_in[19];
    const float* rt0 = (const float*)d_in[20]; const float* bs0 = (const float*)d_in[21];
    const float* nw1 = (const float*)d_in[22]; const float* nb1 = (const float*)d_in[23];
    const float* rt1 = (const float*)d_in[24]; const float* bs1 = (const float*)d_in[25];
    const float* nw2 = (const float*)d_in[26]; const float* nb2 = (const float*)d_in[27];
    const float* rt2 = (const float*)d_in[28]; const float* bs2 = (const float*)d_in[29];
    float* out = (float*)d_out;

    // setup (tiny)
    s1_kernel<<<1, 256>>>(ipw, ipb, Wq_w, Wq_b);
    s2_kernel<<<BB * TT, EMB>>>(gt, Wk_w, Wk_b, Wv_w, Wv_b, ipw, ipb);
    s3_kernel<<<BB, 256>>>(ow);
    trans_kernel<<<(P2N * 1024 + 255) / 256, 256>>>(nw0, 0);
    trans_kernel<<<(P2N * 1024 + 255) / 256, 256>>>(nw1, 1);
    trans_kernel<<<(P2N * 512  + 255) / 256, 256>>>(nw2, 2);

    // stage A: knn interpolate + concat -> d_h0
    knn_kernel<<<MM / 256, 256>>>(x, pos, x_skip, pos_skip);

    // degree
    zero_cnt_kernel<<<MM / 256, 256>>>();
    deg_kernel<<<EE / 256, 256>>>(ei);

    // stage B: attention -> d_pseudo
    attn_kernel<<<EE / 256, 256>>>(ei, pos_skip, ob);

    // stage C: 3 NNConv layers
    // layer 0: d_h0 -> d_h1  (CO=32)
    zero_aggr_kernel<<<MM * CI / 256, 256>>>();
    edge_kernel<32><<<EE / 64, 256>>>(0, ei, nb0);
    node_kernel<32><<<MM / 256, 256>>>(0, rt0, bs0, nullptr, 0);
    // layer 1: d_h1 -> d_h0  (CO=32)
    zero_aggr_kernel<<<MM * CI / 256, 256>>>();
    edge_kernel<32><<<EE / 64, 256>>>(1, ei, nb1);
    node_kernel<32><<<MM / 256, 256>>>(1, rt1, bs1, nullptr, 0);
    // layer 2: d_h0 -> d_out  (CO=16)
    zero_aggr_kernel<<<MM * CI / 256, 256>>>();
    edge_kernel<16><<<EE / 64, 128>>>(2, ei, nb2);
    node_kernel<16><<<MM / 256, 256>>>(2, rt2, bs2, out, out_size);

    // remaining tuple outputs if expected
    tail_kernel<<<(MM * 3 + 255) / 256, 256>>>(pos_skip, batch_sk, out, out_size);
}